// round 6
// baseline (speedup 1.0000x reference)
#include <cuda_runtime.h>
#include <cuda_bf16.h>

#define TOKENS 32768
#define DMODEL 2048
#define NEXP   64
#define TBLK   128
#define KC     32
#define NCHUNK (DMODEL / KC)   // 64
#define NTH    256
#define XP     40              // smem pitch in bf16 elems (80B)
#define LG_LD  68

// stage byte offsets
#define XH_OFF 0
#define XL_OFF 10240
#define WH_OFF 20480
#define WL_OFF 25600
#define STAGE  30720
#define SMEM_DYN (2 * STAGE)

typedef unsigned int u32;
typedef unsigned long long u64;

static __device__ __forceinline__ u32 smem_u32(const void* p) {
    u32 a;
    asm("{ .reg .u64 t; cvta.to.shared.u64 t, %1; cvt.u32.u64 %0, t; }" : "=r"(a) : "l"(p));
    return a;
}

// fp32 -> (bf16_hi, bf16_lo) split of 4 values, packed as u64 pairs
static __device__ __forceinline__ void split4(float4 v, u64& hi, u64& lo) {
    __nv_bfloat162 h01 = __float22bfloat162_rn(make_float2(v.x, v.y));
    __nv_bfloat162 h23 = __float22bfloat162_rn(make_float2(v.z, v.w));
    float2 f01 = __bfloat1622float2(h01);
    float2 f23 = __bfloat1622float2(h23);
    __nv_bfloat162 l01 = __float22bfloat162_rn(make_float2(v.x - f01.x, v.y - f01.y));
    __nv_bfloat162 l23 = __float22bfloat162_rn(make_float2(v.z - f23.x, v.w - f23.y));
    u32 a = *reinterpret_cast<u32*>(&h01);
    u32 b = *reinterpret_cast<u32*>(&h23);
    u32 c = *reinterpret_cast<u32*>(&l01);
    u32 d = *reinterpret_cast<u32*>(&l23);
    hi = (u64)a | ((u64)b << 32);
    lo = (u64)c | ((u64)d << 32);
}

#define LDSM_X4(R, addr)                                                      \
    asm volatile("ldmatrix.sync.aligned.m8n8.x4.shared.b16 {%0,%1,%2,%3}, [%4];" \
        : "=r"((R)[0]), "=r"((R)[1]), "=r"((R)[2]), "=r"((R)[3]) : "r"(addr))

#define MMA_BF16(C, A, B0, B1)                                                \
    asm volatile("mma.sync.aligned.m16n8k16.row.col.f32.bf16.bf16.f32 "       \
        "{%0,%1,%2,%3}, {%4,%5,%6,%7}, {%8,%9}, {%0,%1,%2,%3};"               \
        : "+f"((C)[0]), "+f"((C)[1]), "+f"((C)[2]), "+f"((C)[3])              \
        : "r"((A)[0]), "r"((A)[1]), "r"((A)[2]), "r"((A)[3]), "r"(B0), "r"(B1))

__global__ __launch_bounds__(NTH, 2)
void router_hmma_kernel(const float* __restrict__ x,
                        const float* __restrict__ w,
                        float* __restrict__ out)
{
    extern __shared__ char dsm[];
    __shared__ float inv_s[TBLK];

    const int tid = threadIdx.x;
    const int wid = tid >> 5;
    const int lid = tid & 31;
    const int t0  = blockIdx.x * TBLK;
    const u32 dsm_b = smem_u32(dsm);

    // ---- global load geometry ----
    const int gr = tid >> 3;            // 0..31
    const int gc = tid & 7;             // float4 col in chunk
    const float* xbase = x + (size_t)(t0 + gr) * DMODEL + gc * 4;
    const float* wbase = w + (size_t)gr * DMODEL + gc * 4;
    const u32 sts_off = (u32)((gr * XP + gc * 4) * 2);   // byte offset in tile

    // ---- warp tile: 32 tokens x 32 experts ----
    const int wtok0 = (wid >> 1) * 32;
    const int wexp0 = (wid & 1) * 32;

    // hoisted ldmatrix address components (bytes within stage)
    const int arow = (lid & 7) + ((lid >> 3) & 1) * 8;
    const int acol = ((lid >> 4) & 1) * 8;
    const int brow = (lid & 7) + ((lid >> 4) & 1) * 8;
    const int bcol = ((lid >> 3) & 1) * 8;
    const u32 a_off = (u32)(((wtok0 + arow) * XP + acol) * 2);   // + mt*16*XP*2 + k0*2
    const u32 b_off = (u32)(((wexp0 + brow) * XP + bcol) * 2);   // + ng*16*XP*2 + k0*2

    float acc[2][4][4];
    #pragma unroll
    for (int mt = 0; mt < 2; mt++)
        #pragma unroll
        for (int nt = 0; nt < 4; nt++)
            #pragma unroll
            for (int c = 0; c < 4; c++)
                acc[mt][nt][c] = 0.0f;

    float4 xr[4], wr[2];

    // ---- prologue: chunk 0 -> stage 0; prefetch chunk 1 ----
    #pragma unroll
    for (int i = 0; i < 4; i++) xr[i] = *(const float4*)(xbase + (size_t)i * 32 * DMODEL);
    #pragma unroll
    for (int i = 0; i < 2; i++) wr[i] = *(const float4*)(wbase + (size_t)i * 32 * DMODEL);
    {
        char* st = dsm;
        #pragma unroll
        for (int i = 0; i < 4; i++) {
            u64 hi, lo; split4(xr[i], hi, lo);
            u32 o = sts_off + i * 32 * XP * 2;
            *(u64*)(st + XH_OFF + o) = hi;
            *(u64*)(st + XL_OFF + o) = lo;
        }
        #pragma unroll
        for (int i = 0; i < 2; i++) {
            u64 hi, lo; split4(wr[i], hi, lo);
            u32 o = sts_off + i * 32 * XP * 2;
            *(u64*)(st + WH_OFF + o) = hi;
            *(u64*)(st + WL_OFF + o) = lo;
        }
    }
    #pragma unroll
    for (int i = 0; i < 4; i++) xr[i] = *(const float4*)(xbase + KC + (size_t)i * 32 * DMODEL);
    #pragma unroll
    for (int i = 0; i < 2; i++) wr[i] = *(const float4*)(wbase + KC + (size_t)i * 32 * DMODEL);

    for (int ch = 0; ch < NCHUNK; ++ch) {
        // one barrier per chunk: makes stage (ch&1) writes visible, and
        // protects stage ((ch+1)&1) writes below against last iter's reads.
        __syncthreads();

        // STS next stage from prefetched regs (overlaps with MMA below)
        if (ch + 1 < NCHUNK) {
            char* st = dsm + ((ch + 1) & 1) * STAGE;
            #pragma unroll
            for (int i = 0; i < 4; i++) {
                u64 hi, lo; split4(xr[i], hi, lo);
                u32 o = sts_off + i * 32 * XP * 2;
                *(u64*)(st + XH_OFF + o) = hi;
                *(u64*)(st + XL_OFF + o) = lo;
            }
            #pragma unroll
            for (int i = 0; i < 2; i++) {
                u64 hi, lo; split4(wr[i], hi, lo);
                u32 o = sts_off + i * 32 * XP * 2;
                *(u64*)(st + WH_OFF + o) = hi;
                *(u64*)(st + WL_OFF + o) = lo;
            }
        }
        // prefetch chunk ch+2
        if (ch + 2 < NCHUNK) {
            const int k0 = (ch + 2) * KC;
            #pragma unroll
            for (int i = 0; i < 4; i++)
                xr[i] = *(const float4*)(xbase + k0 + (size_t)i * 32 * DMODEL);
            #pragma unroll
            for (int i = 0; i < 2; i++)
                wr[i] = *(const float4*)(wbase + k0 + (size_t)i * 32 * DMODEL);
        }

        // compute current stage
        const u32 sb = dsm_b + (ch & 1) * STAGE;
        const u32 ah_b = sb + XH_OFF + a_off;
        const u32 al_b = sb + XL_OFF + a_off;
        const u32 bh_b = sb + WH_OFF + b_off;
        const u32 bl_b = sb + WL_OFF + b_off;

        #pragma unroll
        for (int ks = 0; ks < KC / 16; ks++) {
            const u32 ko = ks * 32;   // 16 elems * 2B
            u32 ah[8], al[8], bh[8], bl[8];

            #pragma unroll
            for (int mt = 0; mt < 2; mt++) {
                LDSM_X4(ah + mt * 4, ah_b + mt * (16 * XP * 2) + ko);
                LDSM_X4(al + mt * 4, al_b + mt * (16 * XP * 2) + ko);
            }
            #pragma unroll
            for (int ng = 0; ng < 2; ng++) {
                LDSM_X4(bh + ng * 4, bh_b + ng * (16 * XP * 2) + ko);
                LDSM_X4(bl + ng * 4, bl_b + ng * (16 * XP * 2) + ko);
            }

            #pragma unroll
            for (int mt = 0; mt < 2; mt++)
                #pragma unroll
                for (int nt = 0; nt < 4; nt++) {
                    u32 b0h = bh[nt * 2], b1h = bh[nt * 2 + 1];
                    MMA_BF16(acc[mt][nt], ah + mt * 4, b0h, b1h);              // hi*hi
                    MMA_BF16(acc[mt][nt], al + mt * 4, b0h, b1h);              // lo*hi
                    MMA_BF16(acc[mt][nt], ah + mt * 4, bl[nt * 2], bl[nt * 2 + 1]); // hi*lo
                }
        }
    }

    // ---- epilogue: accs -> smem logits (stage memory dead) ----
    __syncthreads();
    float* logits = (float*)dsm;
    {
        const int crow = lid >> 2;
        const int ccol = (lid & 3) * 2;
        #pragma unroll
        for (int mt = 0; mt < 2; mt++)
            #pragma unroll
            for (int nt = 0; nt < 4; nt++) {
                int tok = wtok0 + mt * 16 + crow;
                int ex  = wexp0 + nt * 8 + ccol;
                *(float2*)&logits[tok * LG_LD + ex] =
                    make_float2(acc[mt][nt][0], acc[mt][nt][1]);
                *(float2*)&logits[(tok + 8) * LG_LD + ex] =
                    make_float2(acc[mt][nt][2], acc[mt][nt][3]);
            }
    }
    __syncthreads();

    if (tid < TBLK) {
        const int t = tid;
        float* row = &logits[t * LG_LD];

        float m1 = -3.4e38f, m2 = -3.4e38f;
        int   i1 = 0,        i2 = 0;
        #pragma unroll
        for (int e = 0; e < NEXP; e++) {
            float v = row[e];
            if (v > m1)      { m2 = m1; i2 = i1; m1 = v; i1 = e; }
            else if (v > m2) { m2 = v; i2 = e; }
        }

        float s = 0.0f;
        #pragma unroll
        for (int e = 0; e < NEXP; e++) {
            float ev = __expf(row[e] - m1);
            row[e] = ev;
            s += ev;
        }
        inv_s[t] = 1.0f / s;

        float e2v = __expf(m2 - m1);
        float g1  = 1.0f / (1.0f + e2v);

        int gt = t0 + t;
        out[2 * gt + 0] = g1;
        out[2 * gt + 1] = e2v * g1;
        float* oidx = out + (size_t)2 * TOKENS;
        oidx[2 * gt + 0] = (float)i1;
        oidx[2 * gt + 1] = (float)i2;
    }
    __syncthreads();

    float* oprob = out + (size_t)4 * TOKENS;
    for (int f = tid; f < TBLK * (NEXP / 4); f += NTH) {
        int r = f >> 4, c4 = f & 15;
        float4 ev = *(const float4*)&logits[r * LG_LD + c4 * 4];
        float inv = inv_s[r];
        float4 p = make_float4(ev.x * inv, ev.y * inv, ev.z * inv, ev.w * inv);
        *(float4*)&oprob[(size_t)(t0 + r) * NEXP + c4 * 4] = p;
    }
}

extern "C" void kernel_launch(void* const* d_in, const int* in_sizes, int n_in,
                              void* d_out, int out_size) {
    const float* x = (const float*)d_in[0];
    const float* w = (const float*)d_in[1];
    float* out = (float*)d_out;
    cudaFuncSetAttribute(router_hmma_kernel,
                         cudaFuncAttributeMaxDynamicSharedMemorySize, SMEM_DYN);
    router_hmma_kernel<<<TOKENS / TBLK, NTH, SMEM_DYN>>>(x, w, out);
}